// round 14
// baseline (speedup 1.0000x reference)
#include <cuda_runtime.h>
#include <cuda_fp16.h>
#include <cstdint>

#define BB 8
#define NN 4096
#define MM 4096
#define KK 64
#define TILE 128
#define MT 4                               // m-tiles per CTA
#define NCTAS ((MM / (TILE * MT)) * (NN / TILE) * BB)   // 2048

#define ROWS_X (BB * NN)
#define ROWS_Y (BB * MM)

typedef unsigned long long ull;

// ---------------- base-ISA PTX helpers ----------------
__device__ __forceinline__ uint32_t smem_to_u32(const void* p) {
    uint32_t a;
    asm("{ .reg .u64 t; cvta.to.shared.u64 t, %1; cvt.u32.u64 %0, t; }" : "=r"(a) : "l"(p));
    return a;
}
__device__ __forceinline__ void ldsm_x4(uint32_t* r, uint32_t addr) {
    asm volatile("ldmatrix.sync.aligned.m8n8.x4.shared.b16 {%0,%1,%2,%3}, [%4];"
                 : "=r"(r[0]), "=r"(r[1]), "=r"(r[2]), "=r"(r[3]) : "r"(addr));
}
__device__ __forceinline__ void mma16816(float* d, const uint32_t* a, const uint32_t* b) {
    asm volatile("mma.sync.aligned.m16n8k16.row.col.f32.f16.f16.f32 "
                 "{%0,%1,%2,%3}, {%4,%5,%6,%7}, {%8,%9}, {%0,%1,%2,%3};"
                 : "+f"(d[0]), "+f"(d[1]), "+f"(d[2]), "+f"(d[3])
                 : "r"(a[0]), "r"(a[1]), "r"(a[2]), "r"(a[3]), "r"(b[0]), "r"(b[1]));
}
__device__ __forceinline__ void cp_async16(uint32_t dst, const void* src) {
    asm volatile("cp.async.cg.shared.global [%0], [%1], 16;" :: "r"(dst), "l"(src) : "memory");
}
#define CP_COMMIT() asm volatile("cp.async.commit_group;" ::: "memory")
#define CP_WAIT(N)  asm volatile("cp.async.wait_group %0;" :: "n"(N) : "memory")
#define SWZ128(off) ((off) ^ (((off) >> 3) & 0x70))

// ---- packed f32x2 fma (base PTX, sm_100+) ----
__device__ __forceinline__ ull pk2(float lo, float hi) {
    ull r; asm("mov.b64 %0, {%1, %2};" : "=l"(r) : "f"(lo), "f"(hi)); return r;
}
__device__ __forceinline__ void upk2(float& lo, float& hi, ull v) {
    asm("mov.b64 {%0, %1}, %2;" : "=f"(lo), "=f"(hi) : "l"(v));
}
__device__ __forceinline__ ull fma2(ull a, ull b, ull c) {   // a*b + c, packed
    ull r; asm("fma.rn.f32x2 %0, %1, %2, %3;" : "=l"(r) : "l"(a), "l"(b), "l"(c));
    return r;
}
#define NEGHALF2 0xBF000000BF000000ULL

// ---------------- device scratch (allocation-free) ----------------
__device__ uint4    g_xh4[ROWS_X * 8];    // 8 uint4 = 64 fp16 per row
__device__ uint4    g_yh4[ROWS_Y * 8];
__device__ float    g_x2[ROWS_X];
__device__ float    g_y2[ROWS_Y];
__device__ unsigned g_rmin[ROWS_X];       // fp32 bits of min clamped sq per (b,n)
__device__ unsigned g_cmin[ROWS_Y];       // fp32 bits of min clamped sq per (b,m)
__device__ unsigned g_ctr = 0;

// -------- convert fp32 -> fp16 (4 threads per row), norms, init mins --------
__global__ void chamfer_convert_kernel(const float* __restrict__ X,
                                       const float* __restrict__ Y) {
    int t = blockIdx.x * blockDim.x + threadIdx.x;   // 262144 threads
    int row = t >> 2;
    int q   = t & 3;
    const float* src;
    uint4* hd;
    float* nrm;
    int idx;
    if (row < ROWS_X) { src = X; hd = g_xh4; nrm = g_x2; idx = row; }
    else              { src = Y; hd = g_yh4; nrm = g_y2; idx = row - ROWS_X; }
    const float4* p = reinterpret_cast<const float4*>(src + (size_t)idx * KK) + q * 4;
    uint4* ho = hd + (size_t)idx * 8 + q * 2;

    float4 v0 = p[0], v1 = p[1], v2 = p[2], v3 = p[3];   // 4 independent loads
    float s = v0.x * v0.x + v0.y * v0.y + v0.z * v0.z + v0.w * v0.w
            + v1.x * v1.x + v1.y * v1.y + v1.z * v1.z + v1.w * v1.w
            + v2.x * v2.x + v2.y * v2.y + v2.z * v2.z + v2.w * v2.w
            + v3.x * v3.x + v3.y * v3.y + v3.z * v3.z + v3.w * v3.w;

    union { uint4 u; __half2 h[4]; } H0, H1;
    H0.h[0] = __floats2half2_rn(v0.x, v0.y);
    H0.h[1] = __floats2half2_rn(v0.z, v0.w);
    H0.h[2] = __floats2half2_rn(v1.x, v1.y);
    H0.h[3] = __floats2half2_rn(v1.z, v1.w);
    H1.h[0] = __floats2half2_rn(v2.x, v2.y);
    H1.h[1] = __floats2half2_rn(v2.z, v2.w);
    H1.h[2] = __floats2half2_rn(v3.x, v3.y);
    H1.h[3] = __floats2half2_rn(v3.z, v3.w);
    ho[0] = H0.u;
    ho[1] = H1.u;

    s += __shfl_xor_sync(0xffffffffu, s, 1);
    s += __shfl_xor_sync(0xffffffffu, s, 2);
    if (q == 0) {
        nrm[idx] = s;
        if (row < ROWS_X) g_rmin[row] = 0x7f800000u;
        else              g_cmin[idx] = 0x7f800000u;
    }
}

// -------- main fused mma.sync kernel (R12-proven) + fused last-CTA reduce --------
// Grid (MM/(128*MT), NN/128, BB) = (8, 32, 8). 256 threads = 8 warps, 4(m) x 2(n).
// acc initialized to -(x2+y2)/2, so post-MMA acc = -sq/2 and min-sq == max-acc.
#define TB (TILE * 128)                    // 16384 B per fp16 tile
#define OFF_XT   0
#define OFF_YT0  (OFF_XT + TB)
#define OFF_YT1  (OFF_YT0 + TB)
#define OFF_YT2  (OFF_YT1 + TB)
#define OFF_X2   (OFF_YT2 + TB)            // 128 floats
#define OFF_Y2B  (OFF_X2 + 512)            // 3 x 128 floats
#define OFF_CMIN (OFF_Y2B + 3 * 512)       // MT x 128 uints
#define SMEM_TOTAL (OFF_CMIN + MT * TILE * 4)

__global__ __launch_bounds__(256, 2)
void chamfer_mma_kernel(float* __restrict__ out) {
    extern __shared__ char smem[];
    __shared__ int   s_last;
    __shared__ float s_red[256];
    uint32_t sb = smem_to_u32(smem);
    const int tid = threadIdx.x;
    const int wid = tid >> 5;
    const int lid = tid & 31;
    const int wr  = wid >> 1;     // m block of 32
    const int wc  = wid & 1;      // n block of 64
    const int b   = blockIdx.z;
    const int n0  = blockIdx.y * TILE;
    const int m0b = blockIdx.x * (TILE * MT);

    float*    x2s    = reinterpret_cast<float*>(smem + OFF_X2);
    unsigned* s_cmin = reinterpret_cast<unsigned*>(smem + OFF_CMIN);
    float*    y2buf[3] = {reinterpret_cast<float*>(smem + OFF_Y2B),
                          reinterpret_cast<float*>(smem + OFF_Y2B + 512),
                          reinterpret_cast<float*>(smem + OFF_Y2B + 1024)};
    const uint32_t ytb[3] = {sb + OFF_YT0, sb + OFF_YT1, sb + OFF_YT2};

    // thread's fill mapping (4 uint4 per tile)
    const int fr0 = tid >> 3;              // rows tid/8 + {0,32,64,96}
    const int fq  = tid & 7;
    uint32_t fdst[4];
    size_t   fsrc[4];
#pragma unroll
    for (int it = 0; it < 4; ++it) {
        int r = fr0 + it * 32;
        fdst[it] = SWZ128((uint32_t)(r * 128 + fq * 16));
        fsrc[it] = (size_t)r * 8 + fq;
    }

    // prologue: group0 = {X, Y0}, group1 = {Y1}
    const uint4* sx = g_xh4 + (size_t)(b * NN + n0) * 8;
    const uint4* sy = g_yh4 + (size_t)(b * MM + m0b) * 8;
#pragma unroll
    for (int it = 0; it < 4; ++it) cp_async16(sb + OFF_XT + fdst[it], sx + fsrc[it]);
#pragma unroll
    for (int it = 0; it < 4; ++it) cp_async16(ytb[0] + fdst[it], sy + fsrc[it]);
    CP_COMMIT();
#pragma unroll
    for (int it = 0; it < 4; ++it) cp_async16(ytb[1] + fdst[it], sy + 1024 + fsrc[it]);
    CP_COMMIT();

    if (tid < 128) x2s[tid] = g_x2[b * NN + n0 + tid];
    else {
        int j = tid - 128;
        y2buf[0][j] = g_y2[b * MM + m0b + j];
        y2buf[1][j] = g_y2[b * MM + m0b + 128 + j];
    }
    s_cmin[tid]       = 0x7f800000u;
    s_cmin[256 + tid] = 0x7f800000u;

    // row maxima of acc (= -sq/2), accumulated across all m-tiles
    float rowM[2][2];
#pragma unroll
    for (int mt = 0; mt < 2; ++mt)
#pragma unroll
        for (int h = 0; h < 2; ++h) rowM[mt][h] = -__int_as_float(0x7f800000);

    ull xh2[2][2];   // packed (-0.5*x2, -0.5*x2) per owned row; loaded after first sync

#pragma unroll
    for (int t = 0; t < MT; ++t) {
        if (t < MT - 1) { CP_WAIT(1); } else { CP_WAIT(0); }
        __syncthreads();   // the ONLY barrier in the loop

        // prefetch Y_{t+2} and its y2 into buffer (t+2)%3 == (t-1)%3
        if (t < MT - 2) {
#pragma unroll
            for (int it = 0; it < 4; ++it)
                cp_async16(ytb[(t + 2) % 3] + fdst[it],
                           sy + (size_t)(t + 2) * 1024 + fsrc[it]);
            CP_COMMIT();
            if (tid < 128)
                y2buf[(t + 2) % 3][tid] = g_y2[b * MM + m0b + (t + 2) * 128 + tid];
        }

        if (t == 0) {
#pragma unroll
            for (int mt = 0; mt < 2; ++mt)
#pragma unroll
                for (int h = 0; h < 2; ++h) {
                    float x = -0.5f * x2s[wr * 32 + mt * 16 + (lid >> 2) + 8 * h];
                    xh2[mt][h] = pk2(x, x);
                }
        }

        const uint32_t Yb = ytb[t % 3];
        const float* y2s  = y2buf[t % 3];

        // raw y2 pairs (8B-aligned contiguous); scaled+added in the packed fma below
        ull y2p[8];
#pragma unroll
        for (int nt = 0; nt < 8; ++nt)
            y2p[nt] = *reinterpret_cast<const ull*>(
                &y2s[wc * 64 + nt * 8 + (lid & 3) * 2]);

        // init acc = fma(y2_pair, -0.5, xh) — one packed FFMA2 per acc-pair
        float acc[2][8][4];
#pragma unroll
        for (int mt = 0; mt < 2; ++mt)
#pragma unroll
            for (int nt = 0; nt < 8; ++nt) {
                ull v0 = fma2(y2p[nt], NEGHALF2, xh2[mt][0]);
                ull v1 = fma2(y2p[nt], NEGHALF2, xh2[mt][1]);
                upk2(acc[mt][nt][0], acc[mt][nt][1], v0);
                upk2(acc[mt][nt][2], acc[mt][nt][3], v1);
            }

#pragma unroll
        for (int ks = 0; ks < 4; ++ks) {
            uint32_t a[2][4];
#pragma unroll
            for (int mt = 0; mt < 2; ++mt) {
                int row  = wr * 32 + mt * 16 + (lid & 15);
                int colb = ks * 32 + (lid >> 4) * 16;
                uint32_t off = (uint32_t)(row * 128 + (colb ^ ((row & 7) * 16)));
                ldsm_x4(a[mt], sb + OFF_XT + off);
            }
            uint32_t bf[4][4];
#pragma unroll
            for (int j2 = 0; j2 < 4; ++j2) {
                int row  = wc * 64 + j2 * 16 + (lid & 7) + ((lid >> 4) & 1) * 8;
                int colb = ks * 32 + ((lid >> 3) & 1) * 16;
                uint32_t off = (uint32_t)(row * 128 + (colb ^ ((row & 7) * 16)));
                ldsm_x4(bf[j2], Yb + off);
            }
#pragma unroll
            for (int mt = 0; mt < 2; ++mt)
#pragma unroll
                for (int nt = 0; nt < 8; ++nt)
                    mma16816(acc[mt][nt], a[mt], &bf[nt >> 1][(nt & 1) * 2]);
        }

        // epilogue: track max acc per row / per col (2 FMNMX per acc, scalar)
        float colM[8][2];
#pragma unroll
        for (int nt = 0; nt < 8; ++nt)
#pragma unroll
            for (int p = 0; p < 2; ++p) colM[nt][p] = -__int_as_float(0x7f800000);

#pragma unroll
        for (int mt = 0; mt < 2; ++mt)
#pragma unroll
            for (int nt = 0; nt < 8; ++nt)
#pragma unroll
                for (int c = 0; c < 4; ++c) {
                    float v = acc[mt][nt][c];
                    rowM[mt][c >> 1] = fmaxf(rowM[mt][c >> 1], v);
                    colM[nt][c & 1]  = fmaxf(colM[nt][c & 1], v);
                }

        // col maxima -> per-tile smem segment (lanes sharing a col differ in lid bits 2-4)
#pragma unroll
        for (int nt = 0; nt < 8; ++nt)
#pragma unroll
            for (int p = 0; p < 2; ++p) {
                float v = colM[nt][p];
                v = fmaxf(v, __shfl_xor_sync(0xffffffffu, v, 4));
                v = fmaxf(v, __shfl_xor_sync(0xffffffffu, v, 8));
                v = fmaxf(v, __shfl_xor_sync(0xffffffffu, v, 16));
                if (lid < 4) {
                    float sq = fmaxf(-2.f * v, 0.f);
                    atomicMin(&s_cmin[t * TILE + wc * 64 + nt * 8 + (lid & 3) * 2 + p],
                              __float_as_uint(sq));
                }
            }
    }

    __syncthreads();   // all per-tile col atomics done

    // single flush of all col mins (MT*128 = 512 contiguous entries)
#pragma unroll
    for (int i = 0; i < (MT * TILE) / 256; ++i) {
        int j = i * 256 + tid;
        atomicMin(&g_cmin[b * MM + m0b + j], s_cmin[j]);
    }

    // row maxima accumulated over all m-tiles; flush once (lid bits 0-1 share a row)
#pragma unroll
    for (int mt = 0; mt < 2; ++mt)
#pragma unroll
        for (int h = 0; h < 2; ++h) {
            float v = rowM[mt][h];
            v = fmaxf(v, __shfl_xor_sync(0xffffffffu, v, 1));
            v = fmaxf(v, __shfl_xor_sync(0xffffffffu, v, 2));
            if ((lid & 3) == 0) {
                float sq = fmaxf(-2.f * v, 0.f);
                atomicMin(&g_rmin[b * NN + n0 + wr * 32 + mt * 16 + (lid >> 2) + 8 * h],
                          __float_as_uint(sq));
            }
        }

    // -------- fused final reduce: last CTA sums sqrt of all mins --------
    __threadfence();
    __syncthreads();
    if (tid == 0) s_last = (atomicAdd(&g_ctr, 1u) == NCTAS - 1u);
    __syncthreads();
    if (s_last) {
        const uint4* rm4 = reinterpret_cast<const uint4*>(g_rmin);
        const uint4* cm4 = reinterpret_cast<const uint4*>(g_cmin);
        float s = 0.f;
#pragma unroll 4
        for (int i = tid; i < ROWS_X / 4; i += 256) {
            uint4 v = rm4[i];
            s += sqrtf(__uint_as_float(v.x)) + sqrtf(__uint_as_float(v.y))
               + sqrtf(__uint_as_float(v.z)) + sqrtf(__uint_as_float(v.w));
        }
#pragma unroll 4
        for (int i = tid; i < ROWS_Y / 4; i += 256) {
            uint4 v = cm4[i];
            s += sqrtf(__uint_as_float(v.x)) + sqrtf(__uint_as_float(v.y))
               + sqrtf(__uint_as_float(v.z)) + sqrtf(__uint_as_float(v.w));
        }
        s_red[tid] = s * (1.f / (float)ROWS_X);   // both sides divide by 32768
        __syncthreads();
        for (int o = 128; o > 0; o >>= 1) {
            if (tid < o) s_red[tid] += s_red[tid + o];
            __syncthreads();
        }
        if (tid == 0) { out[0] = s_red[0]; g_ctr = 0u; }
    }
}

extern "C" void kernel_launch(void* const* d_in, const int* in_sizes, int n_in,
                              void* d_out, int out_size) {
    const float* X = (const float*)d_in[0];  // [B, N, K]
    const float* Y = (const float*)d_in[1];  // [B, M, K]
    float* out = (float*)d_out;

    cudaFuncSetAttribute(chamfer_mma_kernel,
                         cudaFuncAttributeMaxDynamicSharedMemorySize, SMEM_TOTAL);

    chamfer_convert_kernel<<<(4 * (ROWS_X + ROWS_Y)) / 256, 256>>>(X, Y);
    dim3 grid(MM / (TILE * MT), NN / TILE, BB);
    chamfer_mma_kernel<<<grid, 256, SMEM_TOTAL>>>(out);
}

// round 15
// speedup vs baseline: 1.3559x; 1.3559x over previous
#include <cuda_runtime.h>
#include <cuda_fp16.h>
#include <cstdint>

#define BB 8
#define NN 4096
#define MM 4096
#define KK 64
#define TILE 128
#define MT 4                               // m-tiles per CTA

#define ROWS_X (BB * NN)
#define ROWS_Y (BB * MM)

typedef unsigned long long ull;

// ---------------- base-ISA PTX helpers ----------------
__device__ __forceinline__ uint32_t smem_to_u32(const void* p) {
    uint32_t a;
    asm("{ .reg .u64 t; cvta.to.shared.u64 t, %1; cvt.u32.u64 %0, t; }" : "=r"(a) : "l"(p));
    return a;
}
__device__ __forceinline__ void ldsm_x4(uint32_t* r, uint32_t addr) {
    asm volatile("ldmatrix.sync.aligned.m8n8.x4.shared.b16 {%0,%1,%2,%3}, [%4];"
                 : "=r"(r[0]), "=r"(r[1]), "=r"(r[2]), "=r"(r[3]) : "r"(addr));
}
__device__ __forceinline__ void mma16816(float* d, const uint32_t* a, const uint32_t* b) {
    asm volatile("mma.sync.aligned.m16n8k16.row.col.f32.f16.f16.f32 "
                 "{%0,%1,%2,%3}, {%4,%5,%6,%7}, {%8,%9}, {%0,%1,%2,%3};"
                 : "+f"(d[0]), "+f"(d[1]), "+f"(d[2]), "+f"(d[3])
                 : "r"(a[0]), "r"(a[1]), "r"(a[2]), "r"(a[3]), "r"(b[0]), "r"(b[1]));
}
__device__ __forceinline__ void cp_async16(uint32_t dst, const void* src) {
    asm volatile("cp.async.cg.shared.global [%0], [%1], 16;" :: "r"(dst), "l"(src) : "memory");
}
#define CP_COMMIT() asm volatile("cp.async.commit_group;" ::: "memory")
#define CP_WAIT(N)  asm volatile("cp.async.wait_group %0;" :: "n"(N) : "memory")
#define SWZ128(off) ((off) ^ (((off) >> 3) & 0x70))

// ---- packed f32x2 fma (base PTX, sm_100+) ----
__device__ __forceinline__ ull pk2(float lo, float hi) {
    ull r; asm("mov.b64 %0, {%1, %2};" : "=l"(r) : "f"(lo), "f"(hi)); return r;
}
__device__ __forceinline__ void upk2(float& lo, float& hi, ull v) {
    asm("mov.b64 {%0, %1}, %2;" : "=f"(lo), "=f"(hi) : "l"(v));
}
__device__ __forceinline__ ull fma2(ull a, ull b, ull c) {   // a*b + c, packed
    ull r; asm("fma.rn.f32x2 %0, %1, %2, %3;" : "=l"(r) : "l"(a), "l"(b), "l"(c));
    return r;
}
#define NEGHALF2 0xBF000000BF000000ULL

// ---------------- device scratch (allocation-free) ----------------
__device__ uint4    g_xh4[ROWS_X * 8];    // 8 uint4 = 64 fp16 per row
__device__ uint4    g_yh4[ROWS_Y * 8];
__device__ float    g_x2[ROWS_X];
__device__ float    g_y2[ROWS_Y];
__device__ unsigned g_rmin[ROWS_X];       // fp32 bits of min clamped sq per (b,n)
__device__ unsigned g_cmin[ROWS_Y];       // fp32 bits of min clamped sq per (b,m)
__device__ float    g_part[64];
__device__ unsigned g_ctr = 0;

// -------- convert fp32 -> fp16 (4 threads per row), norms, init mins --------
__global__ void chamfer_convert_kernel(const float* __restrict__ X,
                                       const float* __restrict__ Y) {
    int t = blockIdx.x * blockDim.x + threadIdx.x;   // 262144 threads
    int row = t >> 2;
    int q   = t & 3;
    const float* src;
    uint4* hd;
    float* nrm;
    int idx;
    if (row < ROWS_X) { src = X; hd = g_xh4; nrm = g_x2; idx = row; }
    else              { src = Y; hd = g_yh4; nrm = g_y2; idx = row - ROWS_X; }
    const float4* p = reinterpret_cast<const float4*>(src + (size_t)idx * KK) + q * 4;
    uint4* ho = hd + (size_t)idx * 8 + q * 2;

    float4 v0 = p[0], v1 = p[1], v2 = p[2], v3 = p[3];   // 4 independent loads
    float s = v0.x * v0.x + v0.y * v0.y + v0.z * v0.z + v0.w * v0.w
            + v1.x * v1.x + v1.y * v1.y + v1.z * v1.z + v1.w * v1.w
            + v2.x * v2.x + v2.y * v2.y + v2.z * v2.z + v2.w * v2.w
            + v3.x * v3.x + v3.y * v3.y + v3.z * v3.z + v3.w * v3.w;

    union { uint4 u; __half2 h[4]; } H0, H1;
    H0.h[0] = __floats2half2_rn(v0.x, v0.y);
    H0.h[1] = __floats2half2_rn(v0.z, v0.w);
    H0.h[2] = __floats2half2_rn(v1.x, v1.y);
    H0.h[3] = __floats2half2_rn(v1.z, v1.w);
    H1.h[0] = __floats2half2_rn(v2.x, v2.y);
    H1.h[1] = __floats2half2_rn(v2.z, v2.w);
    H1.h[2] = __floats2half2_rn(v3.x, v3.y);
    H1.h[3] = __floats2half2_rn(v3.z, v3.w);
    ho[0] = H0.u;
    ho[1] = H1.u;

    s += __shfl_xor_sync(0xffffffffu, s, 1);
    s += __shfl_xor_sync(0xffffffffu, s, 2);
    if (q == 0) {
        nrm[idx] = s;
        if (row < ROWS_X) g_rmin[row] = 0x7f800000u;
        else              g_cmin[idx] = 0x7f800000u;
    }
}

// -------- main fused mma.sync kernel (R12 revert + register-relief init) --------
// Grid (MM/(128*MT), NN/128, BB) = (8, 32, 8). 256 threads = 8 warps, 4(m) x 2(n).
// acc initialized to -(x2+y2)/2, so post-MMA acc = -sq/2 and min-sq == max-acc.
#define TB (TILE * 128)                    // 16384 B per fp16 tile
#define OFF_XT   0
#define OFF_YT0  (OFF_XT + TB)
#define OFF_YT1  (OFF_YT0 + TB)
#define OFF_YT2  (OFF_YT1 + TB)
#define OFF_X2   (OFF_YT2 + TB)            // 128 floats
#define OFF_Y2B  (OFF_X2 + 512)            // 3 x 128 floats
#define OFF_CMIN (OFF_Y2B + 3 * 512)       // MT x 128 uints
#define SMEM_TOTAL (OFF_CMIN + MT * TILE * 4)

__global__ __launch_bounds__(256, 2)
void chamfer_mma_kernel() {
    extern __shared__ char smem[];
    uint32_t sb = smem_to_u32(smem);
    const int tid = threadIdx.x;
    const int wid = tid >> 5;
    const int lid = tid & 31;
    const int wr  = wid >> 1;     // m block of 32
    const int wc  = wid & 1;      // n block of 64
    const int b   = blockIdx.z;
    const int n0  = blockIdx.y * TILE;
    const int m0b = blockIdx.x * (TILE * MT);

    float*    x2s    = reinterpret_cast<float*>(smem + OFF_X2);
    unsigned* s_cmin = reinterpret_cast<unsigned*>(smem + OFF_CMIN);
    float*    y2buf[3] = {reinterpret_cast<float*>(smem + OFF_Y2B),
                          reinterpret_cast<float*>(smem + OFF_Y2B + 512),
                          reinterpret_cast<float*>(smem + OFF_Y2B + 1024)};
    const uint32_t ytb[3] = {sb + OFF_YT0, sb + OFF_YT1, sb + OFF_YT2};

    // thread's fill mapping (4 uint4 per tile)
    const int fr0 = tid >> 3;              // rows tid/8 + {0,32,64,96}
    const int fq  = tid & 7;
    uint32_t fdst[4];
    size_t   fsrc[4];
#pragma unroll
    for (int it = 0; it < 4; ++it) {
        int r = fr0 + it * 32;
        fdst[it] = SWZ128((uint32_t)(r * 128 + fq * 16));
        fsrc[it] = (size_t)r * 8 + fq;
    }

    // prologue: group0 = {X, Y0}, group1 = {Y1}
    const uint4* sx = g_xh4 + (size_t)(b * NN + n0) * 8;
    const uint4* sy = g_yh4 + (size_t)(b * MM + m0b) * 8;
#pragma unroll
    for (int it = 0; it < 4; ++it) cp_async16(sb + OFF_XT + fdst[it], sx + fsrc[it]);
#pragma unroll
    for (int it = 0; it < 4; ++it) cp_async16(ytb[0] + fdst[it], sy + fsrc[it]);
    CP_COMMIT();
#pragma unroll
    for (int it = 0; it < 4; ++it) cp_async16(ytb[1] + fdst[it], sy + 1024 + fsrc[it]);
    CP_COMMIT();

    if (tid < 128) x2s[tid] = g_x2[b * NN + n0 + tid];
    else {
        int j = tid - 128;
        y2buf[0][j] = g_y2[b * MM + m0b + j];
        y2buf[1][j] = g_y2[b * MM + m0b + 128 + j];
    }
    s_cmin[tid]       = 0x7f800000u;
    s_cmin[256 + tid] = 0x7f800000u;

    // row maxima of acc (= -sq/2), accumulated across all m-tiles
    float rowM[2][2];
#pragma unroll
    for (int mt = 0; mt < 2; ++mt)
#pragma unroll
        for (int h = 0; h < 2; ++h) rowM[mt][h] = -__int_as_float(0x7f800000);

    ull xh2[2][2];   // packed (-0.5*x2, -0.5*x2) per owned row; loaded after first sync

#pragma unroll
    for (int t = 0; t < MT; ++t) {
        if (t < MT - 1) { CP_WAIT(1); } else { CP_WAIT(0); }
        __syncthreads();   // the ONLY barrier in the loop

        // prefetch Y_{t+2} and its y2 into buffer (t+2)%3 == (t-1)%3
        if (t < MT - 2) {
#pragma unroll
            for (int it = 0; it < 4; ++it)
                cp_async16(ytb[(t + 2) % 3] + fdst[it],
                           sy + (size_t)(t + 2) * 1024 + fsrc[it]);
            CP_COMMIT();
            if (tid < 128)
                y2buf[(t + 2) % 3][tid] = g_y2[b * MM + m0b + (t + 2) * 128 + tid];
        }

        if (t == 0) {
#pragma unroll
            for (int mt = 0; mt < 2; ++mt)
#pragma unroll
                for (int h = 0; h < 2; ++h) {
                    float x = -0.5f * x2s[wr * 32 + mt * 16 + (lid >> 2) + 8 * h];
                    xh2[mt][h] = pk2(x, x);
                }
        }

        const uint32_t Yb = ytb[t % 3];
        const float* y2s  = y2buf[t % 3];

        // init acc = fma(y2_pair, -0.5, xh): nt-outer so each y2 pair is one
        // short-lived LDS.64 (frees ~14 regs vs keeping an 8-entry array live)
        float acc[2][8][4];
#pragma unroll
        for (int nt = 0; nt < 8; ++nt) {
            ull yraw = *reinterpret_cast<const ull*>(
                &y2s[wc * 64 + nt * 8 + (lid & 3) * 2]);
#pragma unroll
            for (int mt = 0; mt < 2; ++mt) {
                ull v0 = fma2(yraw, NEGHALF2, xh2[mt][0]);
                ull v1 = fma2(yraw, NEGHALF2, xh2[mt][1]);
                upk2(acc[mt][nt][0], acc[mt][nt][1], v0);
                upk2(acc[mt][nt][2], acc[mt][nt][3], v1);
            }
        }

#pragma unroll
        for (int ks = 0; ks < 4; ++ks) {
            uint32_t a[2][4];
#pragma unroll
            for (int mt = 0; mt < 2; ++mt) {
                int row  = wr * 32 + mt * 16 + (lid & 15);
                int colb = ks * 32 + (lid >> 4) * 16;
                uint32_t off = (uint32_t)(row * 128 + (colb ^ ((row & 7) * 16)));
                ldsm_x4(a[mt], sb + OFF_XT + off);
            }
            uint32_t bf[4][4];
#pragma unroll
            for (int j2 = 0; j2 < 4; ++j2) {
                int row  = wc * 64 + j2 * 16 + (lid & 7) + ((lid >> 4) & 1) * 8;
                int colb = ks * 32 + ((lid >> 3) & 1) * 16;
                uint32_t off = (uint32_t)(row * 128 + (colb ^ ((row & 7) * 16)));
                ldsm_x4(bf[j2], Yb + off);
            }
#pragma unroll
            for (int mt = 0; mt < 2; ++mt)
#pragma unroll
                for (int nt = 0; nt < 8; ++nt)
                    mma16816(acc[mt][nt], a[mt], &bf[nt >> 1][(nt & 1) * 2]);
        }

        // epilogue: track max acc per row / per col (2 FMNMX per acc, scalar)
        float colM[8][2];
#pragma unroll
        for (int nt = 0; nt < 8; ++nt)
#pragma unroll
            for (int p = 0; p < 2; ++p) colM[nt][p] = -__int_as_float(0x7f800000);

#pragma unroll
        for (int mt = 0; mt < 2; ++mt)
#pragma unroll
            for (int nt = 0; nt < 8; ++nt)
#pragma unroll
                for (int c = 0; c < 4; ++c) {
                    float v = acc[mt][nt][c];
                    rowM[mt][c >> 1] = fmaxf(rowM[mt][c >> 1], v);
                    colM[nt][c & 1]  = fmaxf(colM[nt][c & 1], v);
                }

        // col maxima -> per-tile smem segment (lanes sharing a col differ in lid bits 2-4)
#pragma unroll
        for (int nt = 0; nt < 8; ++nt)
#pragma unroll
            for (int p = 0; p < 2; ++p) {
                float v = colM[nt][p];
                v = fmaxf(v, __shfl_xor_sync(0xffffffffu, v, 4));
                v = fmaxf(v, __shfl_xor_sync(0xffffffffu, v, 8));
                v = fmaxf(v, __shfl_xor_sync(0xffffffffu, v, 16));
                if (lid < 4) {
                    float sq = fmaxf(-2.f * v, 0.f);
                    atomicMin(&s_cmin[t * TILE + wc * 64 + nt * 8 + (lid & 3) * 2 + p],
                              __float_as_uint(sq));
                }
            }
    }

    __syncthreads();   // all per-tile col atomics done

    // single flush of all col mins (MT*128 = 512 contiguous entries)
#pragma unroll
    for (int i = 0; i < (MT * TILE) / 256; ++i) {
        int j = i * 256 + tid;
        atomicMin(&g_cmin[b * MM + m0b + j], s_cmin[j]);
    }

    // row maxima accumulated over all m-tiles; flush once (lid bits 0-1 share a row)
#pragma unroll
    for (int mt = 0; mt < 2; ++mt)
#pragma unroll
        for (int h = 0; h < 2; ++h) {
            float v = rowM[mt][h];
            v = fmaxf(v, __shfl_xor_sync(0xffffffffu, v, 1));
            v = fmaxf(v, __shfl_xor_sync(0xffffffffu, v, 2));
            if ((lid & 3) == 0) {
                float sq = fmaxf(-2.f * v, 0.f);
                atomicMin(&g_rmin[b * NN + n0 + wr * 32 + mt * 16 + (lid >> 2) + 8 * h],
                          __float_as_uint(sq));
            }
        }
}

// -------- fused reduce: 64 blocks, uint4 loads (4 mins/thread); last block finishes --------
__global__ void chamfer_reduce_kernel(float* __restrict__ out) {
    __shared__ float red[256];
    __shared__ int is_last;
    const int tid = threadIdx.x;
    const int t = blockIdx.x * 256 + tid;     // 0..16383 (uint4 index)
    uint4 v;
    if (t < ROWS_X / 4) v = reinterpret_cast<const uint4*>(g_rmin)[t];
    else                v = reinterpret_cast<const uint4*>(g_cmin)[t - ROWS_X / 4];
    float s = sqrtf(__uint_as_float(v.x)) + sqrtf(__uint_as_float(v.y))
            + sqrtf(__uint_as_float(v.z)) + sqrtf(__uint_as_float(v.w));
    red[tid] = s * (1.f / (float)ROWS_X);     // both sides divide by 32768
    __syncthreads();
    for (int o = 128; o > 0; o >>= 1) {
        if (tid < o) red[tid] += red[tid + o];
        __syncthreads();
    }
    if (tid == 0) {
        g_part[blockIdx.x] = red[0];
        __threadfence();
        is_last = (atomicAdd(&g_ctr, 1u) == 63u);
    }
    __syncthreads();
    if (is_last) {
        volatile float* vp = g_part;
        red[tid] = (tid < 64) ? vp[tid] : 0.f;
        __syncthreads();
        for (int o = 128; o > 0; o >>= 1) {
            if (tid < o) red[tid] += red[tid + o];
            __syncthreads();
        }
        if (tid == 0) { out[0] = red[0]; g_ctr = 0u; }
    }
}

extern "C" void kernel_launch(void* const* d_in, const int* in_sizes, int n_in,
                              void* d_out, int out_size) {
    const float* X = (const float*)d_in[0];  // [B, N, K]
    const float* Y = (const float*)d_in[1];  // [B, M, K]
    float* out = (float*)d_out;

    cudaFuncSetAttribute(chamfer_mma_kernel,
                         cudaFuncAttributeMaxDynamicSharedMemorySize, SMEM_TOTAL);

    chamfer_convert_kernel<<<(4 * (ROWS_X + ROWS_Y)) / 256, 256>>>(X, Y);
    dim3 grid(MM / (TILE * MT), NN / TILE, BB);
    chamfer_mma_kernel<<<grid, 256, SMEM_TOTAL>>>();
    chamfer_reduce_kernel<<<64, 256>>>(out);
}

// round 16
// speedup vs baseline: 1.3618x; 1.0043x over previous
#include <cuda_runtime.h>
#include <cuda_fp16.h>
#include <cstdint>

#define BB 8
#define NN 4096
#define MM 4096
#define KK 64
#define TILE 128
#define MT 4                               // m-tiles per CTA

#define ROWS_X (BB * NN)
#define ROWS_Y (BB * MM)

typedef unsigned long long ull;

// ---------------- base-ISA PTX helpers ----------------
__device__ __forceinline__ uint32_t smem_to_u32(const void* p) {
    uint32_t a;
    asm("{ .reg .u64 t; cvta.to.shared.u64 t, %1; cvt.u32.u64 %0, t; }" : "=r"(a) : "l"(p));
    return a;
}
__device__ __forceinline__ void ldsm_x4(uint32_t* r, uint32_t addr) {
    asm volatile("ldmatrix.sync.aligned.m8n8.x4.shared.b16 {%0,%1,%2,%3}, [%4];"
                 : "=r"(r[0]), "=r"(r[1]), "=r"(r[2]), "=r"(r[3]) : "r"(addr));
}
__device__ __forceinline__ void mma16816(float* d, const uint32_t* a, const uint32_t* b) {
    asm volatile("mma.sync.aligned.m16n8k16.row.col.f32.f16.f16.f32 "
                 "{%0,%1,%2,%3}, {%4,%5,%6,%7}, {%8,%9}, {%0,%1,%2,%3};"
                 : "+f"(d[0]), "+f"(d[1]), "+f"(d[2]), "+f"(d[3])
                 : "r"(a[0]), "r"(a[1]), "r"(a[2]), "r"(a[3]), "r"(b[0]), "r"(b[1]));
}
__device__ __forceinline__ void cp_async16(uint32_t dst, const void* src) {
    asm volatile("cp.async.cg.shared.global [%0], [%1], 16;" :: "r"(dst), "l"(src) : "memory");
}
#define CP_COMMIT() asm volatile("cp.async.commit_group;" ::: "memory")
#define CP_WAIT(N)  asm volatile("cp.async.wait_group %0;" :: "n"(N) : "memory")
#define SWZ128(off) ((off) ^ (((off) >> 3) & 0x70))

// ---- packed f32x2 fma (base PTX, sm_100+) ----
__device__ __forceinline__ ull pk2(float lo, float hi) {
    ull r; asm("mov.b64 %0, {%1, %2};" : "=l"(r) : "f"(lo), "f"(hi)); return r;
}
__device__ __forceinline__ void upk2(float& lo, float& hi, ull v) {
    asm("mov.b64 {%0, %1}, %2;" : "=f"(lo), "=f"(hi) : "l"(v));
}
__device__ __forceinline__ ull fma2(ull a, ull b, ull c) {   // a*b + c, packed
    ull r; asm("fma.rn.f32x2 %0, %1, %2, %3;" : "=l"(r) : "l"(a), "l"(b), "l"(c));
    return r;
}
#define NEGHALF2 0xBF000000BF000000ULL

// ---------------- device scratch (allocation-free) ----------------
__device__ uint4    g_xh4[ROWS_X * 8];    // 8 uint4 = 64 fp16 per row
__device__ uint4    g_yh4[ROWS_Y * 8];
__device__ float    g_x2[ROWS_X];
__device__ float    g_y2[ROWS_Y];
__device__ unsigned g_rmin[ROWS_X];       // fp32 bits of min clamped sq per (b,n)
__device__ unsigned g_cmin[ROWS_Y];       // fp32 bits of min clamped sq per (b,m)
__device__ float    g_part[64];
__device__ unsigned g_ctr = 0;

// -------- convert fp32 -> fp16 (4 threads per row), norms, init mins --------
__global__ void chamfer_convert_kernel(const float* __restrict__ X,
                                       const float* __restrict__ Y) {
    int t = blockIdx.x * blockDim.x + threadIdx.x;   // 262144 threads
    int row = t >> 2;
    int q   = t & 3;
    const float* src;
    uint4* hd;
    float* nrm;
    int idx;
    if (row < ROWS_X) { src = X; hd = g_xh4; nrm = g_x2; idx = row; }
    else              { src = Y; hd = g_yh4; nrm = g_y2; idx = row - ROWS_X; }
    const float4* p = reinterpret_cast<const float4*>(src + (size_t)idx * KK) + q * 4;
    uint4* ho = hd + (size_t)idx * 8 + q * 2;

    float4 v0 = p[0], v1 = p[1], v2 = p[2], v3 = p[3];   // 4 independent loads
    float s = v0.x * v0.x + v0.y * v0.y + v0.z * v0.z + v0.w * v0.w
            + v1.x * v1.x + v1.y * v1.y + v1.z * v1.z + v1.w * v1.w
            + v2.x * v2.x + v2.y * v2.y + v2.z * v2.z + v2.w * v2.w
            + v3.x * v3.x + v3.y * v3.y + v3.z * v3.z + v3.w * v3.w;

    union { uint4 u; __half2 h[4]; } H0, H1;
    H0.h[0] = __floats2half2_rn(v0.x, v0.y);
    H0.h[1] = __floats2half2_rn(v0.z, v0.w);
    H0.h[2] = __floats2half2_rn(v1.x, v1.y);
    H0.h[3] = __floats2half2_rn(v1.z, v1.w);
    H1.h[0] = __floats2half2_rn(v2.x, v2.y);
    H1.h[1] = __floats2half2_rn(v2.z, v2.w);
    H1.h[2] = __floats2half2_rn(v3.x, v3.y);
    H1.h[3] = __floats2half2_rn(v3.z, v3.w);
    ho[0] = H0.u;
    ho[1] = H1.u;

    s += __shfl_xor_sync(0xffffffffu, s, 1);
    s += __shfl_xor_sync(0xffffffffu, s, 2);
    if (q == 0) {
        nrm[idx] = s;
        if (row < ROWS_X) g_rmin[row] = 0x7f800000u;
        else              g_cmin[idx] = 0x7f800000u;
    }
}

// -------- main fused mma.sync kernel (R12-proven) + XOR-hoisted ldsm addresses --------
// Grid (MM/(128*MT), NN/128, BB) = (8, 32, 8). 256 threads = 8 warps, 4(m) x 2(n).
// acc initialized to -(x2+y2)/2, so post-MMA acc = -sq/2 and min-sq == max-acc.
// Address identity: swizzled addr(ks) = base ^ (ks*32); valid because ks*32 only
// touches bits 5-6 and tile bases are 1024-aligned (SW128 fill already assumes it).
#define TB (TILE * 128)                    // 16384 B per fp16 tile
#define OFF_XT   0
#define OFF_YT0  (OFF_XT + TB)
#define OFF_YT1  (OFF_YT0 + TB)
#define OFF_YT2  (OFF_YT1 + TB)
#define OFF_X2   (OFF_YT2 + TB)            // 128 floats
#define OFF_Y2B  (OFF_X2 + 512)            // 3 x 128 floats
#define OFF_CMIN (OFF_Y2B + 3 * 512)       // MT x 128 uints
#define SMEM_TOTAL (OFF_CMIN + MT * TILE * 4)

__global__ __launch_bounds__(256, 2)
void chamfer_mma_kernel() {
    extern __shared__ char smem[];
    uint32_t sb = smem_to_u32(smem);
    const int tid = threadIdx.x;
    const int wid = tid >> 5;
    const int lid = tid & 31;
    const int wr  = wid >> 1;     // m block of 32
    const int wc  = wid & 1;      // n block of 64
    const int b   = blockIdx.z;
    const int n0  = blockIdx.y * TILE;
    const int m0b = blockIdx.x * (TILE * MT);

    float*    x2s    = reinterpret_cast<float*>(smem + OFF_X2);
    unsigned* s_cmin = reinterpret_cast<unsigned*>(smem + OFF_CMIN);
    float*    y2buf[3] = {reinterpret_cast<float*>(smem + OFF_Y2B),
                          reinterpret_cast<float*>(smem + OFF_Y2B + 512),
                          reinterpret_cast<float*>(smem + OFF_Y2B + 1024)};
    const uint32_t ytb[3] = {sb + OFF_YT0, sb + OFF_YT1, sb + OFF_YT2};

    // thread's fill mapping (4 uint4 per tile)
    const int fr0 = tid >> 3;              // rows tid/8 + {0,32,64,96}
    const int fq  = tid & 7;
    uint32_t fdst[4];
    size_t   fsrc[4];
#pragma unroll
    for (int it = 0; it < 4; ++it) {
        int r = fr0 + it * 32;
        fdst[it] = SWZ128((uint32_t)(r * 128 + fq * 16));
        fsrc[it] = (size_t)r * 8 + fq;
    }

    // prologue: group0 = {X, Y0}, group1 = {Y1}
    const uint4* sx = g_xh4 + (size_t)(b * NN + n0) * 8;
    const uint4* sy = g_yh4 + (size_t)(b * MM + m0b) * 8;
#pragma unroll
    for (int it = 0; it < 4; ++it) cp_async16(sb + OFF_XT + fdst[it], sx + fsrc[it]);
#pragma unroll
    for (int it = 0; it < 4; ++it) cp_async16(ytb[0] + fdst[it], sy + fsrc[it]);
    CP_COMMIT();
#pragma unroll
    for (int it = 0; it < 4; ++it) cp_async16(ytb[1] + fdst[it], sy + 1024 + fsrc[it]);
    CP_COMMIT();

    if (tid < 128) x2s[tid] = g_x2[b * NN + n0 + tid];
    else {
        int j = tid - 128;
        y2buf[0][j] = g_y2[b * MM + m0b + j];
        y2buf[1][j] = g_y2[b * MM + m0b + 128 + j];
    }
    s_cmin[tid]       = 0x7f800000u;
    s_cmin[256 + tid] = 0x7f800000u;

    // XOR-hoisted ldsm bases: X per mt (absolute), B per j2 (tile-relative)
    uint32_t xbase[2];
#pragma unroll
    for (int mt = 0; mt < 2; ++mt) {
        int row = wr * 32 + mt * 16 + (lid & 15);
        uint32_t hi = (uint32_t)((lid >> 4) * 16);
        xbase[mt] = sb + OFF_XT +
            (uint32_t)(row * 128) + (hi ^ (uint32_t)((row & 7) * 16));
    }
    uint32_t bbase[4];
#pragma unroll
    for (int j2 = 0; j2 < 4; ++j2) {
        int row = wc * 64 + j2 * 16 + (lid & 7) + ((lid >> 4) & 1) * 8;
        uint32_t hi = (uint32_t)(((lid >> 3) & 1) * 16);
        bbase[j2] = (uint32_t)(row * 128) + (hi ^ (uint32_t)((row & 7) * 16));
    }

    // row maxima of acc (= -sq/2), accumulated across all m-tiles
    float rowM[2][2];
#pragma unroll
    for (int mt = 0; mt < 2; ++mt)
#pragma unroll
        for (int h = 0; h < 2; ++h) rowM[mt][h] = -__int_as_float(0x7f800000);

    ull xh2[2][2];   // packed (-0.5*x2, -0.5*x2) per owned row; loaded after first sync

#pragma unroll
    for (int t = 0; t < MT; ++t) {
        if (t < MT - 1) { CP_WAIT(1); } else { CP_WAIT(0); }
        __syncthreads();   // the ONLY barrier in the loop

        // prefetch Y_{t+2} and its y2 into buffer (t+2)%3 == (t-1)%3
        if (t < MT - 2) {
#pragma unroll
            for (int it = 0; it < 4; ++it)
                cp_async16(ytb[(t + 2) % 3] + fdst[it],
                           sy + (size_t)(t + 2) * 1024 + fsrc[it]);
            CP_COMMIT();
            if (tid < 128)
                y2buf[(t + 2) % 3][tid] = g_y2[b * MM + m0b + (t + 2) * 128 + tid];
        }

        if (t == 0) {
#pragma unroll
            for (int mt = 0; mt < 2; ++mt)
#pragma unroll
                for (int h = 0; h < 2; ++h) {
                    float x = -0.5f * x2s[wr * 32 + mt * 16 + (lid >> 2) + 8 * h];
                    xh2[mt][h] = pk2(x, x);
                }
        }

        const uint32_t Yb = ytb[t % 3];
        const float* y2s  = y2buf[t % 3];

        // raw y2 pairs (8B-aligned contiguous); scaled+added in the packed fma below
        ull y2p[8];
#pragma unroll
        for (int nt = 0; nt < 8; ++nt)
            y2p[nt] = *reinterpret_cast<const ull*>(
                &y2s[wc * 64 + nt * 8 + (lid & 3) * 2]);

        // init acc = fma(y2_pair, -0.5, xh) — one packed FFMA2 per acc-pair
        float acc[2][8][4];
#pragma unroll
        for (int mt = 0; mt < 2; ++mt)
#pragma unroll
            for (int nt = 0; nt < 8; ++nt) {
                ull v0 = fma2(y2p[nt], NEGHALF2, xh2[mt][0]);
                ull v1 = fma2(y2p[nt], NEGHALF2, xh2[mt][1]);
                upk2(acc[mt][nt][0], acc[mt][nt][1], v0);
                upk2(acc[mt][nt][2], acc[mt][nt][3], v1);
            }

#pragma unroll
        for (int ks = 0; ks < 4; ++ks) {
            const uint32_t kx = (uint32_t)(ks * 32);
            uint32_t a[2][4];
#pragma unroll
            for (int mt = 0; mt < 2; ++mt) ldsm_x4(a[mt], xbase[mt] ^ kx);
            uint32_t bf[4][4];
#pragma unroll
            for (int j2 = 0; j2 < 4; ++j2) ldsm_x4(bf[j2], (Yb + bbase[j2]) ^ kx);
#pragma unroll
            for (int mt = 0; mt < 2; ++mt)
#pragma unroll
                for (int nt = 0; nt < 8; ++nt)
                    mma16816(acc[mt][nt], a[mt], &bf[nt >> 1][(nt & 1) * 2]);
        }

        // epilogue: track max acc per row / per col (2 FMNMX per acc, scalar)
        float colM[8][2];
#pragma unroll
        for (int nt = 0; nt < 8; ++nt)
#pragma unroll
            for (int p = 0; p < 2; ++p) colM[nt][p] = -__int_as_float(0x7f800000);

#pragma unroll
        for (int mt = 0; mt < 2; ++mt)
#pragma unroll
            for (int nt = 0; nt < 8; ++nt)
#pragma unroll
                for (int c = 0; c < 4; ++c) {
                    float v = acc[mt][nt][c];
                    rowM[mt][c >> 1] = fmaxf(rowM[mt][c >> 1], v);
                    colM[nt][c & 1]  = fmaxf(colM[nt][c & 1], v);
                }

        // col maxima -> per-tile smem segment (lanes sharing a col differ in lid bits 2-4)
#pragma unroll
        for (int nt = 0; nt < 8; ++nt)
#pragma unroll
            for (int p = 0; p < 2; ++p) {
                float v = colM[nt][p];
                v = fmaxf(v, __shfl_xor_sync(0xffffffffu, v, 4));
                v = fmaxf(v, __shfl_xor_sync(0xffffffffu, v, 8));
                v = fmaxf(v, __shfl_xor_sync(0xffffffffu, v, 16));
                if (lid < 4) {
                    float sq = fmaxf(-2.f * v, 0.f);
                    atomicMin(&s_cmin[t * TILE + wc * 64 + nt * 8 + (lid & 3) * 2 + p],
                              __float_as_uint(sq));
                }
            }
    }

    __syncthreads();   // all per-tile col atomics done

    // single flush of all col mins (MT*128 = 512 contiguous entries)
#pragma unroll
    for (int i = 0; i < (MT * TILE) / 256; ++i) {
        int j = i * 256 + tid;
        atomicMin(&g_cmin[b * MM + m0b + j], s_cmin[j]);
    }

    // row maxima accumulated over all m-tiles; flush once (lid bits 0-1 share a row)
#pragma unroll
    for (int mt = 0; mt < 2; ++mt)
#pragma unroll
        for (int h = 0; h < 2; ++h) {
            float v = rowM[mt][h];
            v = fmaxf(v, __shfl_xor_sync(0xffffffffu, v, 1));
            v = fmaxf(v, __shfl_xor_sync(0xffffffffu, v, 2));
            if ((lid & 3) == 0) {
                float sq = fmaxf(-2.f * v, 0.f);
                atomicMin(&g_rmin[b * NN + n0 + wr * 32 + mt * 16 + (lid >> 2) + 8 * h],
                          __float_as_uint(sq));
            }
        }
}

// -------- fused reduce: 64 blocks, uint4 loads (4 mins/thread); last block finishes --------
__global__ void chamfer_reduce_kernel(float* __restrict__ out) {
    __shared__ float red[256];
    __shared__ int is_last;
    const int tid = threadIdx.x;
    const int t = blockIdx.x * 256 + tid;     // 0..16383 (uint4 index)
    uint4 v;
    if (t < ROWS_X / 4) v = reinterpret_cast<const uint4*>(g_rmin)[t];
    else                v = reinterpret_cast<const uint4*>(g_cmin)[t - ROWS_X / 4];
    float s = sqrtf(__uint_as_float(v.x)) + sqrtf(__uint_as_float(v.y))
            + sqrtf(__uint_as_float(v.z)) + sqrtf(__uint_as_float(v.w));
    red[tid] = s * (1.f / (float)ROWS_X);     // both sides divide by 32768
    __syncthreads();
    for (int o = 128; o > 0; o >>= 1) {
        if (tid < o) red[tid] += red[tid + o];
        __syncthreads();
    }
    if (tid == 0) {
        g_part[blockIdx.x] = red[0];
        __threadfence();
        is_last = (atomicAdd(&g_ctr, 1u) == 63u);
    }
    __syncthreads();
    if (is_last) {
        volatile float* vp = g_part;
        red[tid] = (tid < 64) ? vp[tid] : 0.f;
        __syncthreads();
        for (int o = 128; o > 0; o >>= 1) {
            if (tid < o) red[tid] += red[tid + o];
            __syncthreads();
        }
        if (tid == 0) { out[0] = red[0]; g_ctr = 0u; }
    }
}

extern "C" void kernel_launch(void* const* d_in, const int* in_sizes, int n_in,
                              void* d_out, int out_size) {
    const float* X = (const float*)d_in[0];  // [B, N, K]
    const float* Y = (const float*)d_in[1];  // [B, M, K]
    float* out = (float*)d_out;

    cudaFuncSetAttribute(chamfer_mma_kernel,
                         cudaFuncAttributeMaxDynamicSharedMemorySize, SMEM_TOTAL);

    chamfer_convert_kernel<<<(4 * (ROWS_X + ROWS_Y)) / 256, 256>>>(X, Y);
    dim3 grid(MM / (TILE * MT), NN / TILE, BB);
    chamfer_mma_kernel<<<grid, 256, SMEM_TOTAL>>>();
    chamfer_reduce_kernel<<<64, 256>>>(out);
}

// round 17
// speedup vs baseline: 1.3657x; 1.0029x over previous
#include <cuda_runtime.h>
#include <cuda_fp16.h>
#include <cstdint>

#define BB 8
#define NN 4096
#define MM 4096
#define KK 64
#define TILE 128
#define MT 4                               // m-tiles per CTA

#define ROWS_X (BB * NN)
#define ROWS_Y (BB * MM)

typedef unsigned long long ull;

// ---------------- base-ISA PTX helpers ----------------
__device__ __forceinline__ uint32_t smem_to_u32(const void* p) {
    uint32_t a;
    asm("{ .reg .u64 t; cvta.to.shared.u64 t, %1; cvt.u32.u64 %0, t; }" : "=r"(a) : "l"(p));
    return a;
}
__device__ __forceinline__ void ldsm_x4(uint32_t* r, uint32_t addr) {
    asm volatile("ldmatrix.sync.aligned.m8n8.x4.shared.b16 {%0,%1,%2,%3}, [%4];"
                 : "=r"(r[0]), "=r"(r[1]), "=r"(r[2]), "=r"(r[3]) : "r"(addr));
}
__device__ __forceinline__ void mma16816(float* d, const uint32_t* a, const uint32_t* b) {
    asm volatile("mma.sync.aligned.m16n8k16.row.col.f32.f16.f16.f32 "
                 "{%0,%1,%2,%3}, {%4,%5,%6,%7}, {%8,%9}, {%0,%1,%2,%3};"
                 : "+f"(d[0]), "+f"(d[1]), "+f"(d[2]), "+f"(d[3])
                 : "r"(a[0]), "r"(a[1]), "r"(a[2]), "r"(a[3]), "r"(b[0]), "r"(b[1]));
}
__device__ __forceinline__ void cp_async16(uint32_t dst, const void* src) {
    asm volatile("cp.async.cg.shared.global [%0], [%1], 16;" :: "r"(dst), "l"(src) : "memory");
}
#define CP_COMMIT() asm volatile("cp.async.commit_group;" ::: "memory")
#define CP_WAIT(N)  asm volatile("cp.async.wait_group %0;" :: "n"(N) : "memory")
#define SWZ128(off) ((off) ^ (((off) >> 3) & 0x70))

// ---- packed f32x2 fma (base PTX, sm_100+) ----
__device__ __forceinline__ ull pk2(float lo, float hi) {
    ull r; asm("mov.b64 %0, {%1, %2};" : "=l"(r) : "f"(lo), "f"(hi)); return r;
}
__device__ __forceinline__ void upk2(float& lo, float& hi, ull v) {
    asm("mov.b64 {%0, %1}, %2;" : "=f"(lo), "=f"(hi) : "l"(v));
}
__device__ __forceinline__ ull fma2(ull a, ull b, ull c) {   // a*b + c, packed
    ull r; asm("fma.rn.f32x2 %0, %1, %2, %3;" : "=l"(r) : "l"(a), "l"(b), "l"(c));
    return r;
}
#define NEGHALF2 0xBF000000BF000000ULL

// ---------------- device scratch (allocation-free) ----------------
__device__ uint4    g_xh4[ROWS_X * 8];    // 8 uint4 = 64 fp16 per row
__device__ uint4    g_yh4[ROWS_Y * 8];
__device__ float    g_x2[ROWS_X];
__device__ float    g_y2[ROWS_Y];
__device__ unsigned g_rmin[ROWS_X];       // fp32 bits of min clamped sq per (b,n)
__device__ unsigned g_cmin[ROWS_Y];       // fp32 bits of min clamped sq per (b,m)
__device__ float    g_part[64];
__device__ unsigned g_ctr = 0;

// -------- convert fp32 -> fp16 (4 threads per row), norms, init mins --------
__global__ void chamfer_convert_kernel(const float* __restrict__ X,
                                       const float* __restrict__ Y) {
    int t = blockIdx.x * blockDim.x + threadIdx.x;   // 262144 threads
    int row = t >> 2;
    int q   = t & 3;
    const float* src;
    uint4* hd;
    float* nrm;
    int idx;
    if (row < ROWS_X) { src = X; hd = g_xh4; nrm = g_x2; idx = row; }
    else              { src = Y; hd = g_yh4; nrm = g_y2; idx = row - ROWS_X; }
    const float4* p = reinterpret_cast<const float4*>(src + (size_t)idx * KK) + q * 4;
    uint4* ho = hd + (size_t)idx * 8 + q * 2;

    float4 v0 = p[0], v1 = p[1], v2 = p[2], v3 = p[3];   // 4 independent loads
    float s = v0.x * v0.x + v0.y * v0.y + v0.z * v0.z + v0.w * v0.w
            + v1.x * v1.x + v1.y * v1.y + v1.z * v1.z + v1.w * v1.w
            + v2.x * v2.x + v2.y * v2.y + v2.z * v2.z + v2.w * v2.w
            + v3.x * v3.x + v3.y * v3.y + v3.z * v3.z + v3.w * v3.w;

    union { uint4 u; __half2 h[4]; } H0, H1;
    H0.h[0] = __floats2half2_rn(v0.x, v0.y);
    H0.h[1] = __floats2half2_rn(v0.z, v0.w);
    H0.h[2] = __floats2half2_rn(v1.x, v1.y);
    H0.h[3] = __floats2half2_rn(v1.z, v1.w);
    H1.h[0] = __floats2half2_rn(v2.x, v2.y);
    H1.h[1] = __floats2half2_rn(v2.z, v2.w);
    H1.h[2] = __floats2half2_rn(v3.x, v3.y);
    H1.h[3] = __floats2half2_rn(v3.z, v3.w);
    ho[0] = H0.u;
    ho[1] = H1.u;

    s += __shfl_xor_sync(0xffffffffu, s, 1);
    s += __shfl_xor_sync(0xffffffffu, s, 2);
    if (q == 0) {
        nrm[idx] = s;
        if (row < ROWS_X) g_rmin[row] = 0x7f800000u;
        else              g_cmin[idx] = 0x7f800000u;
    }
}

// -------- main fused mma.sync kernel: persistent X, 4 Y tiles, 3-buffer ring,
//          segmented col-min smem, ONE barrier per m-tile, FFMA2 packed init --------
// Grid (MM/(128*MT), NN/128, BB) = (8, 32, 8). 256 threads = 8 warps, 4(m) x 2(n).
// acc initialized to -(x2+y2)/2, so post-MMA acc = -sq/2 and min-sq == max-acc.
#define TB (TILE * 128)                    // 16384 B per fp16 tile
#define OFF_XT   0
#define OFF_YT0  (OFF_XT + TB)
#define OFF_YT1  (OFF_YT0 + TB)
#define OFF_YT2  (OFF_YT1 + TB)
#define OFF_X2   (OFF_YT2 + TB)            // 128 floats
#define OFF_Y2B  (OFF_X2 + 512)            // 3 x 128 floats
#define OFF_CMIN (OFF_Y2B + 3 * 512)       // MT x 128 uints
#define SMEM_TOTAL (OFF_CMIN + MT * TILE * 4)

__global__ __launch_bounds__(256, 2)
void chamfer_mma_kernel() {
    extern __shared__ char smem[];
    uint32_t sb = smem_to_u32(smem);
    const int tid = threadIdx.x;
    const int wid = tid >> 5;
    const int lid = tid & 31;
    const int wr  = wid >> 1;     // m block of 32
    const int wc  = wid & 1;      // n block of 64
    const int b   = blockIdx.z;
    const int n0  = blockIdx.y * TILE;
    const int m0b = blockIdx.x * (TILE * MT);

    float*    x2s    = reinterpret_cast<float*>(smem + OFF_X2);
    unsigned* s_cmin = reinterpret_cast<unsigned*>(smem + OFF_CMIN);
    float*    y2buf[3] = {reinterpret_cast<float*>(smem + OFF_Y2B),
                          reinterpret_cast<float*>(smem + OFF_Y2B + 512),
                          reinterpret_cast<float*>(smem + OFF_Y2B + 1024)};
    const uint32_t ytb[3] = {sb + OFF_YT0, sb + OFF_YT1, sb + OFF_YT2};

    // thread's fill mapping (4 uint4 per tile)
    const int fr0 = tid >> 3;              // rows tid/8 + {0,32,64,96}
    const int fq  = tid & 7;
    uint32_t fdst[4];
    size_t   fsrc[4];
#pragma unroll
    for (int it = 0; it < 4; ++it) {
        int r = fr0 + it * 32;
        fdst[it] = SWZ128((uint32_t)(r * 128 + fq * 16));
        fsrc[it] = (size_t)r * 8 + fq;
    }

    // prologue: group0 = {X, Y0}, group1 = {Y1}
    const uint4* sx = g_xh4 + (size_t)(b * NN + n0) * 8;
    const uint4* sy = g_yh4 + (size_t)(b * MM + m0b) * 8;
#pragma unroll
    for (int it = 0; it < 4; ++it) cp_async16(sb + OFF_XT + fdst[it], sx + fsrc[it]);
#pragma unroll
    for (int it = 0; it < 4; ++it) cp_async16(ytb[0] + fdst[it], sy + fsrc[it]);
    CP_COMMIT();
#pragma unroll
    for (int it = 0; it < 4; ++it) cp_async16(ytb[1] + fdst[it], sy + 1024 + fsrc[it]);
    CP_COMMIT();

    if (tid < 128) x2s[tid] = g_x2[b * NN + n0 + tid];
    else {
        int j = tid - 128;
        y2buf[0][j] = g_y2[b * MM + m0b + j];
        y2buf[1][j] = g_y2[b * MM + m0b + 128 + j];
    }
    s_cmin[tid]       = 0x7f800000u;
    s_cmin[256 + tid] = 0x7f800000u;

    // row maxima of acc (= -sq/2), accumulated across all m-tiles
    float rowM[2][2];
#pragma unroll
    for (int mt = 0; mt < 2; ++mt)
#pragma unroll
        for (int h = 0; h < 2; ++h) rowM[mt][h] = -__int_as_float(0x7f800000);

    ull xh2[2][2];   // packed (-0.5*x2, -0.5*x2) per owned row; loaded after first sync

#pragma unroll
    for (int t = 0; t < MT; ++t) {
        if (t < MT - 1) { CP_WAIT(1); } else { CP_WAIT(0); }
        __syncthreads();   // the ONLY barrier in the loop

        // prefetch Y_{t+2} and its y2 into buffer (t+2)%3 == (t-1)%3
        if (t < MT - 2) {
#pragma unroll
            for (int it = 0; it < 4; ++it)
                cp_async16(ytb[(t + 2) % 3] + fdst[it],
                           sy + (size_t)(t + 2) * 1024 + fsrc[it]);
            CP_COMMIT();
            if (tid < 128)
                y2buf[(t + 2) % 3][tid] = g_y2[b * MM + m0b + (t + 2) * 128 + tid];
        }

        if (t == 0) {
#pragma unroll
            for (int mt = 0; mt < 2; ++mt)
#pragma unroll
                for (int h = 0; h < 2; ++h) {
                    float x = -0.5f * x2s[wr * 32 + mt * 16 + (lid >> 2) + 8 * h];
                    xh2[mt][h] = pk2(x, x);
                }
        }

        const uint32_t Yb = ytb[t % 3];
        const float* y2s  = y2buf[t % 3];

        // raw y2 pairs (8B-aligned contiguous); scaled+added in the packed fma below
        ull y2p[8];
#pragma unroll
        for (int nt = 0; nt < 8; ++nt)
            y2p[nt] = *reinterpret_cast<const ull*>(
                &y2s[wc * 64 + nt * 8 + (lid & 3) * 2]);

        // init acc = fma(y2_pair, -0.5, xh) — one packed FFMA2 per acc-pair
        float acc[2][8][4];
#pragma unroll
        for (int mt = 0; mt < 2; ++mt)
#pragma unroll
            for (int nt = 0; nt < 8; ++nt) {
                ull v0 = fma2(y2p[nt], NEGHALF2, xh2[mt][0]);
                ull v1 = fma2(y2p[nt], NEGHALF2, xh2[mt][1]);
                upk2(acc[mt][nt][0], acc[mt][nt][1], v0);
                upk2(acc[mt][nt][2], acc[mt][nt][3], v1);
            }

#pragma unroll
        for (int ks = 0; ks < 4; ++ks) {
            uint32_t a[2][4];
#pragma unroll
            for (int mt = 0; mt < 2; ++mt) {
                int row  = wr * 32 + mt * 16 + (lid & 15);
                int colb = ks * 32 + (lid >> 4) * 16;
                uint32_t off = (uint32_t)(row * 128 + (colb ^ ((row & 7) * 16)));
                ldsm_x4(a[mt], sb + OFF_XT + off);
            }
            uint32_t bf[4][4];
#pragma unroll
            for (int j2 = 0; j2 < 4; ++j2) {
                int row  = wc * 64 + j2 * 16 + (lid & 7) + ((lid >> 4) & 1) * 8;
                int colb = ks * 32 + ((lid >> 3) & 1) * 16;
                uint32_t off = (uint32_t)(row * 128 + (colb ^ ((row & 7) * 16)));
                ldsm_x4(bf[j2], Yb + off);
            }
#pragma unroll
            for (int mt = 0; mt < 2; ++mt)
#pragma unroll
                for (int nt = 0; nt < 8; ++nt)
                    mma16816(acc[mt][nt], a[mt], &bf[nt >> 1][(nt & 1) * 2]);
        }

        // epilogue: track max acc per row / per col (2 FMNMX per acc, scalar)
        float colM[8][2];
#pragma unroll
        for (int nt = 0; nt < 8; ++nt)
#pragma unroll
            for (int p = 0; p < 2; ++p) colM[nt][p] = -__int_as_float(0x7f800000);

#pragma unroll
        for (int mt = 0; mt < 2; ++mt)
#pragma unroll
            for (int nt = 0; nt < 8; ++nt)
#pragma unroll
                for (int c = 0; c < 4; ++c) {
                    float v = acc[mt][nt][c];
                    rowM[mt][c >> 1] = fmaxf(rowM[mt][c >> 1], v);
                    colM[nt][c & 1]  = fmaxf(colM[nt][c & 1], v);
                }

        // col maxima -> per-tile smem segment (lanes sharing a col differ in lid bits 2-4)
#pragma unroll
        for (int nt = 0; nt < 8; ++nt)
#pragma unroll
            for (int p = 0; p < 2; ++p) {
                float v = colM[nt][p];
                v = fmaxf(v, __shfl_xor_sync(0xffffffffu, v, 4));
                v = fmaxf(v, __shfl_xor_sync(0xffffffffu, v, 8));
                v = fmaxf(v, __shfl_xor_sync(0xffffffffu, v, 16));
                if (lid < 4) {
                    float sq = fmaxf(-2.f * v, 0.f);
                    atomicMin(&s_cmin[t * TILE + wc * 64 + nt * 8 + (lid & 3) * 2 + p],
                              __float_as_uint(sq));
                }
            }
    }

    __syncthreads();   // all per-tile col atomics done

    // single flush of all col mins (MT*128 = 512 contiguous entries)
#pragma unroll
    for (int i = 0; i < (MT * TILE) / 256; ++i) {
        int j = i * 256 + tid;
        atomicMin(&g_cmin[b * MM + m0b + j], s_cmin[j]);
    }

    // row maxima accumulated over all m-tiles; flush once (lid bits 0-1 share a row)
#pragma unroll
    for (int mt = 0; mt < 2; ++mt)
#pragma unroll
        for (int h = 0; h < 2; ++h) {
            float v = rowM[mt][h];
            v = fmaxf(v, __shfl_xor_sync(0xffffffffu, v, 1));
            v = fmaxf(v, __shfl_xor_sync(0xffffffffu, v, 2));
            if ((lid & 3) == 0) {
                float sq = fmaxf(-2.f * v, 0.f);
                atomicMin(&g_rmin[b * NN + n0 + wr * 32 + mt * 16 + (lid >> 2) + 8 * h],
                          __float_as_uint(sq));
            }
        }
}

// -------- fused reduce: 64 blocks, uint4 loads (4 mins/thread); last block finishes --------
__global__ void chamfer_reduce_kernel(float* __restrict__ out) {
    __shared__ float red[256];
    __shared__ int is_last;
    const int tid = threadIdx.x;
    const int t = blockIdx.x * 256 + tid;     // 0..16383 (uint4 index)
    uint4 v;
    if (t < ROWS_X / 4) v = reinterpret_cast<const uint4*>(g_rmin)[t];
    else                v = reinterpret_cast<const uint4*>(g_cmin)[t - ROWS_X / 4];
    float s = sqrtf(__uint_as_float(v.x)) + sqrtf(__uint_as_float(v.y))
            + sqrtf(__uint_as_float(v.z)) + sqrtf(__uint_as_float(v.w));
    red[tid] = s * (1.f / (float)ROWS_X);     // both sides divide by 32768
    __syncthreads();
    for (int o = 128; o > 0; o >>= 1) {
        if (tid < o) red[tid] += red[tid + o];
        __syncthreads();
    }
    if (tid == 0) {
        g_part[blockIdx.x] = red[0];
        __threadfence();
        is_last = (atomicAdd(&g_ctr, 1u) == 63u);
    }
    __syncthreads();
    if (is_last) {
        volatile float* vp = g_part;
        red[tid] = (tid < 64) ? vp[tid] : 0.f;
        __syncthreads();
        for (int o = 128; o > 0; o >>= 1) {
            if (tid < o) red[tid] += red[tid + o];
            __syncthreads();
        }
        if (tid == 0) { out[0] = red[0]; g_ctr = 0u; }
    }
}

extern "C" void kernel_launch(void* const* d_in, const int* in_sizes, int n_in,
                              void* d_out, int out_size) {
    const float* X = (const float*)d_in[0];  // [B, N, K]
    const float* Y = (const float*)d_in[1];  // [B, M, K]
    float* out = (float*)d_out;

    cudaFuncSetAttribute(chamfer_mma_kernel,
                         cudaFuncAttributeMaxDynamicSharedMemorySize, SMEM_TOTAL);

    chamfer_convert_kernel<<<(4 * (ROWS_X + ROWS_Y)) / 256, 256>>>(X, Y);
    dim3 grid(MM / (TILE * MT), NN / TILE, BB);
    chamfer_mma_kernel<<<grid, 256, SMEM_TOTAL>>>();
    chamfer_reduce_kernel<<<64, 256>>>(out);
}